// round 1
// baseline (speedup 1.0000x reference)
#include <cuda_runtime.h>
#include <mma.h>
#include <math.h>

using namespace nvcuda;

// ---------------------------------------------------------------------------
// Problem: 2-layer LSTM cell + 2-layer MLP head, all fp32.
//   B=4096, N_I=1024, N_H1=1024, N_H2=1024, N_H3=2048, N_H4=1024
// All GEMMs are TN: C[m,n] = sum_k A[m,k] * W[n,k], A row-major [M,K],
// W row-major [N,K]. Accuracy via tf32x3 split (hi/lo) on wmma tensor cores.
// ---------------------------------------------------------------------------

#define BM 64
#define BN 32
#define BK 16
#define LDAS 24   // padded SMEM stride (multiple of 8 for 32B-aligned frag ptrs)
#define LDBS 24
#define NTHREADS 256

// Scratch for out3 = relu(h2 @ W3^T + b3): [4096, 2048] fp32 (no cudaMalloc allowed)
__device__ float g_out3[4096 * 2048];

__device__ __forceinline__ float tf32_trunc(float x) {
    return __uint_as_float(__float_as_uint(x) & 0xFFFFE000u);
}
__device__ __forceinline__ float sigm(float x) { return 1.0f / (1.0f + expf(-x)); }

using FragA = wmma::fragment<wmma::matrix_a, 16, 16, 8, wmma::precision::tf32, wmma::row_major>;
using FragB = wmma::fragment<wmma::matrix_b, 16, 16, 8, wmma::precision::tf32, wmma::col_major>;
using FragC = wmma::fragment<wmma::accumulator, 16, 16, 8, float>;

template <class F>
__device__ __forceinline__ void cvt_tf32(F& f) {
#pragma unroll
    for (int i = 0; i < f.num_elements; i++) f.x[i] = wmma::__float_to_tf32(f.x[i]);
}

// ---------------------------------------------------------------------------
// Fused LSTM layer: computes all 4 gate GEMMs (f, i, c, o) over the virtual
// concatenation A = [A1 | A2] (K1 + K2 = K columns), then the cell update:
//   f = sig(zWf+bf); i = sig(zWi+bi); cand = tanh(zWc+bc); o = sig(zWo+bo)
//   h_new = o * tanh(cand)           (double tanh, faithful to reference)
//   c_new = f * c_old + cand * i
// ---------------------------------------------------------------------------
__global__ void __launch_bounds__(NTHREADS)
lstm_kernel(const float* __restrict__ A1, const float* __restrict__ A2,
            int K1, int K,
            const float* __restrict__ Wf, const float* __restrict__ Wi,
            const float* __restrict__ Wc, const float* __restrict__ Wo,
            const float* __restrict__ bf, const float* __restrict__ bi,
            const float* __restrict__ bc, const float* __restrict__ bo,
            const float* __restrict__ c_old,
            float* __restrict__ h_out, float* __restrict__ c_out, int N)
{
    extern __shared__ float smem[];
    float* Ah = smem;                       // BM * LDAS
    float* Al = Ah + BM * LDAS;             // BM * LDAS
    float* Bh = Al + BM * LDAS;             // 4 * BN * LDBS
    float* Bl = Bh + 4 * BN * LDBS;         // 4 * BN * LDBS

    const int tid = threadIdx.x;
    const int wid = tid >> 5;
    const int wm = wid >> 1;    // 0..3 : 16-row slab within BM
    const int wn = wid & 1;     // 0..1 : 16-col slab within BN
    const int m0 = blockIdx.y * BM;
    const int n0 = blockIdx.x * BN;
    const int K2 = K - K1;

    FragC acc[4];
#pragma unroll
    for (int g = 0; g < 4; g++) wmma::fill_fragment(acc[g], 0.0f);

    for (int k0 = 0; k0 < K; k0 += BK) {
        // ---- load A tile (BM x BK): 1 float4 per thread, split hi/lo ----
        {
            int row = tid >> 2;
            int c4  = (tid & 3) << 2;
            int gk  = k0 + c4;
            const float* src = (gk < K1) ? (A1 + (size_t)(m0 + row) * K1 + gk)
                                         : (A2 + (size_t)(m0 + row) * K2 + (gk - K1));
            float4 v = *reinterpret_cast<const float4*>(src);
            float hx = tf32_trunc(v.x), hy = tf32_trunc(v.y);
            float hz = tf32_trunc(v.z), hw = tf32_trunc(v.w);
            float* ah = Ah + row * LDAS + c4;
            float* al = Al + row * LDAS + c4;
            ah[0] = hx; ah[1] = hy; ah[2] = hz; ah[3] = hw;
            al[0] = v.x - hx; al[1] = v.y - hy; al[2] = v.z - hz; al[3] = v.w - hw;
        }
        // ---- load B tiles (4 gates x BN x BK): 2 float4 per thread ----
        for (int t = tid; t < 512; t += NTHREADS) {
            int g  = t >> 7;
            int r  = (t >> 2) & 31;
            int c4 = (t & 3) << 2;
            const float* Wp = (g == 0) ? Wf : (g == 1) ? Wi : (g == 2) ? Wc : Wo;
            float4 v = *reinterpret_cast<const float4*>(Wp + (size_t)(n0 + r) * K + k0 + c4);
            float hx = tf32_trunc(v.x), hy = tf32_trunc(v.y);
            float hz = tf32_trunc(v.z), hw = tf32_trunc(v.w);
            float* bh = Bh + g * (BN * LDBS) + r * LDBS + c4;
            float* bl = Bl + g * (BN * LDBS) + r * LDBS + c4;
            bh[0] = hx; bh[1] = hy; bh[2] = hz; bh[3] = hw;
            bl[0] = v.x - hx; bl[1] = v.y - hy; bl[2] = v.z - hz; bl[3] = v.w - hw;
        }
        __syncthreads();

#pragma unroll
        for (int ks = 0; ks < BK; ks += 8) {
            FragA a_hi, a_lo;
            wmma::load_matrix_sync(a_hi, Ah + (wm * 16) * LDAS + ks, LDAS);
            wmma::load_matrix_sync(a_lo, Al + (wm * 16) * LDAS + ks, LDAS);
            cvt_tf32(a_hi); cvt_tf32(a_lo);
#pragma unroll
            for (int g = 0; g < 4; g++) {
                FragB b_hi, b_lo;
                const float* pbh = Bh + g * (BN * LDBS) + (wn * 16) * LDBS + ks;
                const float* pbl = Bl + g * (BN * LDBS) + (wn * 16) * LDBS + ks;
                wmma::load_matrix_sync(b_hi, pbh, LDBS);
                wmma::load_matrix_sync(b_lo, pbl, LDBS);
                cvt_tf32(b_hi); cvt_tf32(b_lo);
                wmma::mma_sync(acc[g], a_hi, b_hi, acc[g]);   // hi*hi
                wmma::mma_sync(acc[g], a_hi, b_lo, acc[g]);   // hi*lo
                wmma::mma_sync(acc[g], a_lo, b_hi, acc[g]);   // lo*hi
            }
        }
        __syncthreads();
    }

    // ---- epilogue: stage 4 gate tiles in SMEM, then fuse the cell update ----
    float* Cs = smem;   // 4 * BM * BN floats (32KB), reuses mainloop SMEM
#pragma unroll
    for (int g = 0; g < 4; g++)
        wmma::store_matrix_sync(Cs + g * (BM * BN) + (wm * 16) * BN + wn * 16,
                                acc[g], BN, wmma::mem_row_major);
    __syncthreads();

#pragma unroll
    for (int it = 0; it < (BM * BN) / NTHREADS; it++) {
        int e  = tid + it * NTHREADS;
        int mr = e >> 5;          // BN == 32
        int nc = e & 31;
        int gm = m0 + mr;
        int gn = n0 + nc;
        float fv = sigm(Cs[0 * (BM * BN) + e] + bf[gn]);
        float iv = sigm(Cs[1 * (BM * BN) + e] + bi[gn]);
        float cd = tanhf(Cs[2 * (BM * BN) + e] + bc[gn]);
        float ov = sigm(Cs[3 * (BM * BN) + e] + bo[gn]);
        float hv = ov * tanhf(cd);                      // double tanh (as reference)
        float cv = fv * c_old[(size_t)gm * N + gn] + cd * iv;
        h_out[(size_t)gm * N + gn] = hv;
        c_out[(size_t)gm * N + gn] = cv;
    }
}

// ---------------------------------------------------------------------------
// MLP GEMM: out = act(A @ W^T + b). A==nullptr -> read g_out3; out==nullptr ->
// write g_out3 (avoids cudaGetSymbolAddress on the host side).
// ---------------------------------------------------------------------------
template <bool RELU>
__global__ void __launch_bounds__(NTHREADS)
mlp_kernel(const float* __restrict__ A_in, int K,
           const float* __restrict__ W, const float* __restrict__ b,
           float* __restrict__ out_in, int N)
{
    const float* A = A_in ? A_in : (const float*)g_out3;
    float* out     = out_in ? out_in : g_out3;

    extern __shared__ float smem[];
    float* Ah = smem;                  // BM * LDAS
    float* Al = Ah + BM * LDAS;
    float* Bh = Al + BM * LDAS;        // BN * LDBS
    float* Bl = Bh + BN * LDBS;

    const int tid = threadIdx.x;
    const int wid = tid >> 5;
    const int wm = wid >> 1;
    const int wn = wid & 1;
    const int m0 = blockIdx.y * BM;
    const int n0 = blockIdx.x * BN;

    FragC acc;
    wmma::fill_fragment(acc, 0.0f);

    for (int k0 = 0; k0 < K; k0 += BK) {
        {
            int row = tid >> 2;
            int c4  = (tid & 3) << 2;
            float4 v = *reinterpret_cast<const float4*>(A + (size_t)(m0 + row) * K + k0 + c4);
            float hx = tf32_trunc(v.x), hy = tf32_trunc(v.y);
            float hz = tf32_trunc(v.z), hw = tf32_trunc(v.w);
            float* ah = Ah + row * LDAS + c4;
            float* al = Al + row * LDAS + c4;
            ah[0] = hx; ah[1] = hy; ah[2] = hz; ah[3] = hw;
            al[0] = v.x - hx; al[1] = v.y - hy; al[2] = v.z - hz; al[3] = v.w - hw;
        }
        if (tid < 128) {
            int r  = tid >> 2;
            int c4 = (tid & 3) << 2;
            float4 v = *reinterpret_cast<const float4*>(W + (size_t)(n0 + r) * K + k0 + c4);
            float hx = tf32_trunc(v.x), hy = tf32_trunc(v.y);
            float hz = tf32_trunc(v.z), hw = tf32_trunc(v.w);
            float* bh = Bh + r * LDBS + c4;
            float* bl = Bl + r * LDBS + c4;
            bh[0] = hx; bh[1] = hy; bh[2] = hz; bh[3] = hw;
            bl[0] = v.x - hx; bl[1] = v.y - hy; bl[2] = v.z - hz; bl[3] = v.w - hw;
        }
        __syncthreads();

#pragma unroll
        for (int ks = 0; ks < BK; ks += 8) {
            FragA a_hi, a_lo;
            wmma::load_matrix_sync(a_hi, Ah + (wm * 16) * LDAS + ks, LDAS);
            wmma::load_matrix_sync(a_lo, Al + (wm * 16) * LDAS + ks, LDAS);
            cvt_tf32(a_hi); cvt_tf32(a_lo);
            FragB b_hi, b_lo;
            wmma::load_matrix_sync(b_hi, Bh + (wn * 16) * LDBS + ks, LDBS);
            wmma::load_matrix_sync(b_lo, Bl + (wn * 16) * LDBS + ks, LDBS);
            cvt_tf32(b_hi); cvt_tf32(b_lo);
            wmma::mma_sync(acc, a_hi, b_hi, acc);
            wmma::mma_sync(acc, a_hi, b_lo, acc);
            wmma::mma_sync(acc, a_lo, b_hi, acc);
        }
        __syncthreads();
    }

    float* Cs = smem;   // BM * BN
    wmma::store_matrix_sync(Cs + (wm * 16) * BN + wn * 16, acc, BN, wmma::mem_row_major);
    __syncthreads();

#pragma unroll
    for (int it = 0; it < (BM * BN) / NTHREADS; it++) {
        int e  = tid + it * NTHREADS;
        int mr = e >> 5;
        int nc = e & 31;
        float v = Cs[e] + b[n0 + nc];
        if (RELU) v = fmaxf(v, 0.0f);
        out[(size_t)(m0 + mr) * N + (n0 + nc)] = v;
    }
}

// ---------------------------------------------------------------------------
// Launch: 4 dependent kernels on the default (capture) stream.
// Inputs (metadata order):
//  0 X, 1 hidden1, 2 hidden2, 3 cell1, 4 cell2,
//  5 Wf1, 6 bf1, 7 Wi1, 8 bi1, 9 Wc1, 10 bc1, 11 Wo1, 12 bo1,
// 13 Wf2, 14 bf2, 15 Wi2, 16 bi2, 17 Wc2, 18 bc2, 19 Wo2, 20 bo2,
// 21 W3, 22 b3, 23 W4, 24 b4
// Output: concat(out, h1, h2, c1, c2), each [4096,1024] fp32.
// ---------------------------------------------------------------------------
extern "C" void kernel_launch(void* const* d_in, const int* in_sizes, int n_in,
                              void* d_out, int out_size) {
    (void)in_sizes; (void)n_in; (void)out_size;
    const float* X    = (const float*)d_in[0];
    const float* h1in = (const float*)d_in[1];
    const float* h2in = (const float*)d_in[2];
    const float* c1in = (const float*)d_in[3];
    const float* c2in = (const float*)d_in[4];
    const float* Wf1 = (const float*)d_in[5];  const float* bf1 = (const float*)d_in[6];
    const float* Wi1 = (const float*)d_in[7];  const float* bi1 = (const float*)d_in[8];
    const float* Wc1 = (const float*)d_in[9];  const float* bc1 = (const float*)d_in[10];
    const float* Wo1 = (const float*)d_in[11]; const float* bo1 = (const float*)d_in[12];
    const float* Wf2 = (const float*)d_in[13]; const float* bf2 = (const float*)d_in[14];
    const float* Wi2 = (const float*)d_in[15]; const float* bi2 = (const float*)d_in[16];
    const float* Wc2 = (const float*)d_in[17]; const float* bc2 = (const float*)d_in[18];
    const float* Wo2 = (const float*)d_in[19]; const float* bo2 = (const float*)d_in[20];
    const float* W3  = (const float*)d_in[21]; const float* b3  = (const float*)d_in[22];
    const float* W4  = (const float*)d_in[23]; const float* b4  = (const float*)d_in[24];

    const int Bsz = 4096, NI = 1024, NH1 = 1024, NH2 = 1024, NH3 = 2048, NH4 = 1024;

    float* out  = (float*)d_out;
    float* o_h1 = out  + (size_t)Bsz * NH4;
    float* o_h2 = o_h1 + (size_t)Bsz * NH1;
    float* o_c1 = o_h2 + (size_t)Bsz * NH2;
    float* o_c2 = o_c1 + (size_t)Bsz * NH1;

    const size_t smem_lstm = (size_t)(2 * BM * LDAS + 2 * 4 * BN * LDBS) * sizeof(float); // 36864
    const size_t smem_mlp  = (size_t)(2 * BM * LDAS + 2 * BN * LDBS) * sizeof(float);     // 18432

    dim3 blk(NTHREADS);

    // LSTM layer 1: z = [X | hidden1], K = 2048
    lstm_kernel<<<dim3(NH1 / BN, Bsz / BM), blk, smem_lstm>>>(
        X, h1in, NI, NI + NH1,
        Wf1, Wi1, Wc1, Wo1, bf1, bi1, bc1, bo1,
        c1in, o_h1, o_c1, NH1);

    // LSTM layer 2: z = [h1 | hidden2], K = 2048
    lstm_kernel<<<dim3(NH2 / BN, Bsz / BM), blk, smem_lstm>>>(
        o_h1, h2in, NH1, NH1 + NH2,
        Wf2, Wi2, Wc2, Wo2, bf2, bi2, bc2, bo2,
        c2in, o_h2, o_c2, NH2);

    // MLP: out3 = relu(h2 @ W3^T + b3)  -> g_out3 scratch
    mlp_kernel<true><<<dim3(NH3 / BN, Bsz / BM), blk, smem_mlp>>>(
        o_h2, NH2, W3, b3, nullptr, NH3);

    // MLP: out = out3 @ W4^T + b4
    mlp_kernel<false><<<dim3(NH4 / BN, Bsz / BM), blk, smem_mlp>>>(
        nullptr, NH3, W4, b4, out, NH4);
}

// round 2
// speedup vs baseline: 1.0015x; 1.0015x over previous
#include <cuda_runtime.h>
#include <mma.h>
#include <math.h>

using namespace nvcuda;

// ---------------------------------------------------------------------------
// Problem: 2-layer LSTM cell + 2-layer MLP head, all fp32.
//   B=4096, N_I=1024, N_H1=1024, N_H2=1024, N_H3=2048, N_H4=1024
// All GEMMs are TN: C[m,n] = sum_k A[m,k] * W[n,k], A row-major [M,K],
// W row-major [N,K]. Accuracy via tf32x3 split (hi/lo) on wmma tensor cores.
// ---------------------------------------------------------------------------

#define BM 64
#define BN 32
#define BK 16
#define LDAS 24   // padded SMEM stride (multiple of 8 for 32B-aligned frag ptrs)
#define LDBS 24
#define NTHREADS 256

// Scratch for out3 = relu(h2 @ W3^T + b3): [4096, 2048] fp32 (no cudaMalloc allowed)
__device__ float g_out3[4096 * 2048];

__device__ __forceinline__ float tf32_trunc(float x) {
    return __uint_as_float(__float_as_uint(x) & 0xFFFFE000u);
}
__device__ __forceinline__ float sigm(float x) { return 1.0f / (1.0f + expf(-x)); }

using FragA = wmma::fragment<wmma::matrix_a, 16, 16, 8, wmma::precision::tf32, wmma::row_major>;
using FragB = wmma::fragment<wmma::matrix_b, 16, 16, 8, wmma::precision::tf32, wmma::col_major>;
using FragC = wmma::fragment<wmma::accumulator, 16, 16, 8, float>;

template <class F>
__device__ __forceinline__ void cvt_tf32(F& f) {
#pragma unroll
    for (int i = 0; i < f.num_elements; i++) f.x[i] = wmma::__float_to_tf32(f.x[i]);
}

// ---------------------------------------------------------------------------
// Fused LSTM layer: computes all 4 gate GEMMs (f, i, c, o) over the virtual
// concatenation A = [A1 | A2] (K1 + K2 = K columns), then the cell update:
//   f = sig(zWf+bf); i = sig(zWi+bi); cand = tanh(zWc+bc); o = sig(zWo+bo)
//   h_new = o * tanh(cand)           (double tanh, faithful to reference)
//   c_new = f * c_old + cand * i
// ---------------------------------------------------------------------------
__global__ void __launch_bounds__(NTHREADS)
lstm_kernel(const float* __restrict__ A1, const float* __restrict__ A2,
            int K1, int K,
            const float* __restrict__ Wf, const float* __restrict__ Wi,
            const float* __restrict__ Wc, const float* __restrict__ Wo,
            const float* __restrict__ bf, const float* __restrict__ bi,
            const float* __restrict__ bc, const float* __restrict__ bo,
            const float* __restrict__ c_old,
            float* __restrict__ h_out, float* __restrict__ c_out, int N)
{
    extern __shared__ float smem[];
    float* Ah = smem;                       // BM * LDAS
    float* Al = Ah + BM * LDAS;             // BM * LDAS
    float* Bh = Al + BM * LDAS;             // 4 * BN * LDBS
    float* Bl = Bh + 4 * BN * LDBS;         // 4 * BN * LDBS

    const int tid = threadIdx.x;
    const int wid = tid >> 5;
    const int wm = wid >> 1;    // 0..3 : 16-row slab within BM
    const int wn = wid & 1;     // 0..1 : 16-col slab within BN
    const int m0 = blockIdx.y * BM;
    const int n0 = blockIdx.x * BN;
    const int K2 = K - K1;

    FragC acc[4];
#pragma unroll
    for (int g = 0; g < 4; g++) wmma::fill_fragment(acc[g], 0.0f);

    for (int k0 = 0; k0 < K; k0 += BK) {
        // ---- load A tile (BM x BK): 1 float4 per thread, split hi/lo ----
        {
            int row = tid >> 2;
            int c4  = (tid & 3) << 2;
            int gk  = k0 + c4;
            const float* src = (gk < K1) ? (A1 + (size_t)(m0 + row) * K1 + gk)
                                         : (A2 + (size_t)(m0 + row) * K2 + (gk - K1));
            float4 v = *reinterpret_cast<const float4*>(src);
            float hx = tf32_trunc(v.x), hy = tf32_trunc(v.y);
            float hz = tf32_trunc(v.z), hw = tf32_trunc(v.w);
            float* ah = Ah + row * LDAS + c4;
            float* al = Al + row * LDAS + c4;
            ah[0] = hx; ah[1] = hy; ah[2] = hz; ah[3] = hw;
            al[0] = v.x - hx; al[1] = v.y - hy; al[2] = v.z - hz; al[3] = v.w - hw;
        }
        // ---- load B tiles (4 gates x BN x BK): 2 float4 per thread ----
        for (int t = tid; t < 512; t += NTHREADS) {
            int g  = t >> 7;
            int r  = (t >> 2) & 31;
            int c4 = (t & 3) << 2;
            const float* Wp = (g == 0) ? Wf : (g == 1) ? Wi : (g == 2) ? Wc : Wo;
            float4 v = *reinterpret_cast<const float4*>(Wp + (size_t)(n0 + r) * K + k0 + c4);
            float hx = tf32_trunc(v.x), hy = tf32_trunc(v.y);
            float hz = tf32_trunc(v.z), hw = tf32_trunc(v.w);
            float* bh = Bh + g * (BN * LDBS) + r * LDBS + c4;
            float* bl = Bl + g * (BN * LDBS) + r * LDBS + c4;
            bh[0] = hx; bh[1] = hy; bh[2] = hz; bh[3] = hw;
            bl[0] = v.x - hx; bl[1] = v.y - hy; bl[2] = v.z - hz; bl[3] = v.w - hw;
        }
        __syncthreads();

#pragma unroll
        for (int ks = 0; ks < BK; ks += 8) {
            FragA a_hi, a_lo;
            wmma::load_matrix_sync(a_hi, Ah + (wm * 16) * LDAS + ks, LDAS);
            wmma::load_matrix_sync(a_lo, Al + (wm * 16) * LDAS + ks, LDAS);
            cvt_tf32(a_hi); cvt_tf32(a_lo);
#pragma unroll
            for (int g = 0; g < 4; g++) {
                FragB b_hi, b_lo;
                const float* pbh = Bh + g * (BN * LDBS) + (wn * 16) * LDBS + ks;
                const float* pbl = Bl + g * (BN * LDBS) + (wn * 16) * LDBS + ks;
                wmma::load_matrix_sync(b_hi, pbh, LDBS);
                wmma::load_matrix_sync(b_lo, pbl, LDBS);
                cvt_tf32(b_hi); cvt_tf32(b_lo);
                wmma::mma_sync(acc[g], a_hi, b_hi, acc[g]);   // hi*hi
                wmma::mma_sync(acc[g], a_hi, b_lo, acc[g]);   // hi*lo
                wmma::mma_sync(acc[g], a_lo, b_hi, acc[g]);   // lo*hi
            }
        }
        __syncthreads();
    }

    // ---- epilogue: stage 4 gate tiles in SMEM, then fuse the cell update ----
    float* Cs = smem;   // 4 * BM * BN floats (32KB), reuses mainloop SMEM
#pragma unroll
    for (int g = 0; g < 4; g++)
        wmma::store_matrix_sync(Cs + g * (BM * BN) + (wm * 16) * BN + wn * 16,
                                acc[g], BN, wmma::mem_row_major);
    __syncthreads();

#pragma unroll
    for (int it = 0; it < (BM * BN) / NTHREADS; it++) {
        int e  = tid + it * NTHREADS;
        int mr = e >> 5;          // BN == 32
        int nc = e & 31;
        int gm = m0 + mr;
        int gn = n0 + nc;
        float fv = sigm(Cs[0 * (BM * BN) + e] + bf[gn]);
        float iv = sigm(Cs[1 * (BM * BN) + e] + bi[gn]);
        float cd = tanhf(Cs[2 * (BM * BN) + e] + bc[gn]);
        float ov = sigm(Cs[3 * (BM * BN) + e] + bo[gn]);
        float hv = ov * tanhf(cd);                      // double tanh (as reference)
        float cv = fv * c_old[(size_t)gm * N + gn] + cd * iv;
        h_out[(size_t)gm * N + gn] = hv;
        c_out[(size_t)gm * N + gn] = cv;
    }
}

// ---------------------------------------------------------------------------
// MLP GEMM: out = act(A @ W^T + b). A==nullptr -> read g_out3; out==nullptr ->
// write g_out3 (avoids cudaGetSymbolAddress on the host side).
// ---------------------------------------------------------------------------
template <bool RELU>
__global__ void __launch_bounds__(NTHREADS)
mlp_kernel(const float* __restrict__ A_in, int K,
           const float* __restrict__ W, const float* __restrict__ b,
           float* __restrict__ out_in, int N)
{
    const float* A = A_in ? A_in : (const float*)g_out3;
    float* out     = out_in ? out_in : g_out3;

    extern __shared__ float smem[];
    float* Ah = smem;                  // BM * LDAS
    float* Al = Ah + BM * LDAS;
    float* Bh = Al + BM * LDAS;        // BN * LDBS
    float* Bl = Bh + BN * LDBS;

    const int tid = threadIdx.x;
    const int wid = tid >> 5;
    const int wm = wid >> 1;
    const int wn = wid & 1;
    const int m0 = blockIdx.y * BM;
    const int n0 = blockIdx.x * BN;

    FragC acc;
    wmma::fill_fragment(acc, 0.0f);

    for (int k0 = 0; k0 < K; k0 += BK) {
        {
            int row = tid >> 2;
            int c4  = (tid & 3) << 2;
            float4 v = *reinterpret_cast<const float4*>(A + (size_t)(m0 + row) * K + k0 + c4);
            float hx = tf32_trunc(v.x), hy = tf32_trunc(v.y);
            float hz = tf32_trunc(v.z), hw = tf32_trunc(v.w);
            float* ah = Ah + row * LDAS + c4;
            float* al = Al + row * LDAS + c4;
            ah[0] = hx; ah[1] = hy; ah[2] = hz; ah[3] = hw;
            al[0] = v.x - hx; al[1] = v.y - hy; al[2] = v.z - hz; al[3] = v.w - hw;
        }
        if (tid < 128) {
            int r  = tid >> 2;
            int c4 = (tid & 3) << 2;
            float4 v = *reinterpret_cast<const float4*>(W + (size_t)(n0 + r) * K + k0 + c4);
            float hx = tf32_trunc(v.x), hy = tf32_trunc(v.y);
            float hz = tf32_trunc(v.z), hw = tf32_trunc(v.w);
            float* bh = Bh + r * LDBS + c4;
            float* bl = Bl + r * LDBS + c4;
            bh[0] = hx; bh[1] = hy; bh[2] = hz; bh[3] = hw;
            bl[0] = v.x - hx; bl[1] = v.y - hy; bl[2] = v.z - hz; bl[3] = v.w - hw;
        }
        __syncthreads();

#pragma unroll
        for (int ks = 0; ks < BK; ks += 8) {
            FragA a_hi, a_lo;
            wmma::load_matrix_sync(a_hi, Ah + (wm * 16) * LDAS + ks, LDAS);
            wmma::load_matrix_sync(a_lo, Al + (wm * 16) * LDAS + ks, LDAS);
            cvt_tf32(a_hi); cvt_tf32(a_lo);
            FragB b_hi, b_lo;
            wmma::load_matrix_sync(b_hi, Bh + (wn * 16) * LDBS + ks, LDBS);
            wmma::load_matrix_sync(b_lo, Bl + (wn * 16) * LDBS + ks, LDBS);
            cvt_tf32(b_hi); cvt_tf32(b_lo);
            wmma::mma_sync(acc, a_hi, b_hi, acc);
            wmma::mma_sync(acc, a_hi, b_lo, acc);
            wmma::mma_sync(acc, a_lo, b_hi, acc);
        }
        __syncthreads();
    }

    float* Cs = smem;   // BM * BN
    wmma::store_matrix_sync(Cs + (wm * 16) * BN + wn * 16, acc, BN, wmma::mem_row_major);
    __syncthreads();

#pragma unroll
    for (int it = 0; it < (BM * BN) / NTHREADS; it++) {
        int e  = tid + it * NTHREADS;
        int mr = e >> 5;
        int nc = e & 31;
        float v = Cs[e] + b[n0 + nc];
        if (RELU) v = fmaxf(v, 0.0f);
        out[(size_t)(m0 + mr) * N + (n0 + nc)] = v;
    }
}

// ---------------------------------------------------------------------------
// Launch: 4 dependent kernels on the default (capture) stream.
// Inputs (metadata order):
//  0 X, 1 hidden1, 2 hidden2, 3 cell1, 4 cell2,
//  5 Wf1, 6 bf1, 7 Wi1, 8 bi1, 9 Wc1, 10 bc1, 11 Wo1, 12 bo1,
// 13 Wf2, 14 bf2, 15 Wi2, 16 bi2, 17 Wc2, 18 bc2, 19 Wo2, 20 bo2,
// 21 W3, 22 b3, 23 W4, 24 b4
// Output: concat(out, h1, h2, c1, c2), each [4096,1024] fp32.
// ---------------------------------------------------------------------------
extern "C" void kernel_launch(void* const* d_in, const int* in_sizes, int n_in,
                              void* d_out, int out_size) {
    (void)in_sizes; (void)n_in; (void)out_size;
    const float* X    = (const float*)d_in[0];
    const float* h1in = (const float*)d_in[1];
    const float* h2in = (const float*)d_in[2];
    const float* c1in = (const float*)d_in[3];
    const float* c2in = (const float*)d_in[4];
    const float* Wf1 = (const float*)d_in[5];  const float* bf1 = (const float*)d_in[6];
    const float* Wi1 = (const float*)d_in[7];  const float* bi1 = (const float*)d_in[8];
    const float* Wc1 = (const float*)d_in[9];  const float* bc1 = (const float*)d_in[10];
    const float* Wo1 = (const float*)d_in[11]; const float* bo1 = (const float*)d_in[12];
    const float* Wf2 = (const float*)d_in[13]; const float* bf2 = (const float*)d_in[14];
    const float* Wi2 = (const float*)d_in[15]; const float* bi2 = (const float*)d_in[16];
    const float* Wc2 = (const float*)d_in[17]; const float* bc2 = (const float*)d_in[18];
    const float* Wo2 = (const float*)d_in[19]; const float* bo2 = (const float*)d_in[20];
    const float* W3  = (const float*)d_in[21]; const float* b3  = (const float*)d_in[22];
    const float* W4  = (const float*)d_in[23]; const float* b4  = (const float*)d_in[24];

    const int Bsz = 4096, NI = 1024, NH1 = 1024, NH2 = 1024, NH3 = 2048, NH4 = 1024;

    float* out  = (float*)d_out;
    float* o_h1 = out  + (size_t)Bsz * NH4;
    float* o_h2 = o_h1 + (size_t)Bsz * NH1;
    float* o_c1 = o_h2 + (size_t)Bsz * NH2;
    float* o_c2 = o_c1 + (size_t)Bsz * NH1;

    const size_t smem_lstm = (size_t)(2 * BM * LDAS + 2 * 4 * BN * LDBS) * sizeof(float); // 36864
    const size_t smem_mlp  = (size_t)(2 * BM * LDAS + 2 * BN * LDBS) * sizeof(float);     // 18432

    dim3 blk(NTHREADS);

    // LSTM layer 1: z = [X | hidden1], K = 2048
    lstm_kernel<<<dim3(NH1 / BN, Bsz / BM), blk, smem_lstm>>>(
        X, h1in, NI, NI + NH1,
        Wf1, Wi1, Wc1, Wo1, bf1, bi1, bc1, bo1,
        c1in, o_h1, o_c1, NH1);

    // LSTM layer 2: z = [h1 | hidden2], K = 2048
    lstm_kernel<<<dim3(NH2 / BN, Bsz / BM), blk, smem_lstm>>>(
        o_h1, h2in, NH1, NH1 + NH2,
        Wf2, Wi2, Wc2, Wo2, bf2, bi2, bc2, bo2,
        c2in, o_h2, o_c2, NH2);

    // MLP: out3 = relu(h2 @ W3^T + b3)  -> g_out3 scratch
    mlp_kernel<true><<<dim3(NH3 / BN, Bsz / BM), blk, smem_mlp>>>(
        o_h2, NH2, W3, b3, nullptr, NH3);

    // MLP: out = out3 @ W4^T + b4
    mlp_kernel<false><<<dim3(NH4 / BN, Bsz / BM), blk, smem_mlp>>>(
        nullptr, NH3, W4, b4, out, NH4);
}

// round 4
// speedup vs baseline: 5.0720x; 5.0642x over previous
#include <cuda_runtime.h>
#include <cuda_bf16.h>
#include <math.h>
#include <stdint.h>

// ============================================================================
// QueST: 2-layer LSTM cell + 2-layer MLP head, fp32 semantics.
// Engine: mma.sync.m16n8k16 bf16 (baseline PTX — tcgen05 is rejected by the
// harness's compute_103 PTX pass), bf16x3 split for fp32-class accuracy.
// CTA tile 128x128, warp tile 32x64, cp.async double-buffered K=64 chunks.
// ============================================================================

#define SWZ(o)     ((o) ^ (((o) >> 3) & 0x70))
#define STAGE_B    65536                 // Ahi 16K | Alo 16K | Bhi 16K | Blo 16K
#define SMEM_BYTES (2 * STAGE_B)         // 131072
#define CSTRIDE    132                   // epilogue f32 stage stride (pad 4)

// ---- scratch (no cudaMalloc allowed) ---------------------------------------
__device__ __nv_bfloat16 g_w[41943040];    // weight splits: W1(hi,lo) W2 W3 W4
__device__ __nv_bfloat16 g_A1s[16777216];  // [4096,2048] hi + lo   (X | h1_in)
__device__ __nv_bfloat16 g_A2s[16777216];  // [4096,2048] hi + lo   (h1 | h2_in)
__device__ __nv_bfloat16 g_h2s[8388608];   // [4096,1024] hi + lo
__device__ __nv_bfloat16 g_o3s[16777216];  // [4096,2048] hi + lo

// ---- helpers -----------------------------------------------------------------
__device__ __forceinline__ uint32_t smem_u32(const void* p) {
    uint32_t a;
    asm("{ .reg .u64 t; cvta.to.shared.u64 t, %1; cvt.u32.u64 %0, t; }"
        : "=r"(a) : "l"(p));
    return a;
}
__device__ __forceinline__ void cp16(uint32_t dst, const void* src) {
    asm volatile("cp.async.cg.shared.global [%0], [%1], 16;" :: "r"(dst), "l"(src));
}
__device__ __forceinline__ void cp_commit() {
    asm volatile("cp.async.commit_group;" ::: "memory");
}
__device__ __forceinline__ void cp_wait1() {
    asm volatile("cp.async.wait_group 1;" ::: "memory");
}
__device__ __forceinline__ void ldsm4(uint32_t& r0, uint32_t& r1, uint32_t& r2,
                                      uint32_t& r3, uint32_t a) {
    asm volatile("ldmatrix.sync.aligned.m8n8.x4.shared.b16 {%0,%1,%2,%3}, [%4];"
                 : "=r"(r0), "=r"(r1), "=r"(r2), "=r"(r3) : "r"(a));
}
__device__ __forceinline__ void mma16816(float* d, const uint32_t* a,
                                         uint32_t b0, uint32_t b1) {
    asm volatile(
        "mma.sync.aligned.m16n8k16.row.col.f32.bf16.bf16.f32 "
        "{%0,%1,%2,%3}, {%4,%5,%6,%7}, {%8,%9}, {%0,%1,%2,%3};"
        : "+f"(d[0]), "+f"(d[1]), "+f"(d[2]), "+f"(d[3])
        : "r"(a[0]), "r"(a[1]), "r"(a[2]), "r"(a[3]), "r"(b0), "r"(b1));
}
__device__ __forceinline__ float sigm(float x) { return 1.0f / (1.0f + expf(-x)); }

// ---- GEMM mainloop: acc[128,128] += A[128,K] * Wblob[128,K]^T (bf16x3) -------
__device__ __forceinline__ void gemm_mainloop(
    const __nv_bfloat16* __restrict__ Ahi, const __nv_bfloat16* __restrict__ Alo,
    const __nv_bfloat16* __restrict__ Bhi, const __nv_bfloat16* __restrict__ Blo,
    int K, int m0, int n0b, char* smem, float acc[2][8][4])
{
    const uint32_t sb = smem_u32(smem);
    const int tid  = threadIdx.x;
    const int lane = tid & 31;
    const int wid  = tid >> 5;
    const int wm   = wid & 3;    // m-warp 0..3 -> 32 rows each
    const int wn   = wid >> 2;   // n-warp 0..1 -> 64 cols each

    const __nv_bfloat16* PAh = Ahi + (size_t)m0 * K;
    const __nv_bfloat16* PAl = Alo + (size_t)m0 * K;
    const __nv_bfloat16* PBh = Bhi + (size_t)n0b * K;
    const __nv_bfloat16* PBl = Blo + (size_t)n0b * K;

    const int r  = tid >> 3;          // 0..31 (row group per 256-thread sweep)
    const int c8 = (tid & 7) * 8;     // k element offset (16B chunks)

    // per sub-tile: 128 rows x 64 k bf16 = 1024 x 16B; 4 iters of 256 threads
#define LOAD_STAGE(buf, k0)                                                      \
    {                                                                            \
        uint32_t base = sb + (buf) * STAGE_B;                                    \
        _Pragma("unroll")                                                        \
        for (int it = 0; it < 4; it++) {                                         \
            int rr = r + it * 32;                                                \
            uint32_t so = SWZ(rr * 128 + c8 * 2);                                \
            cp16(base +          so, PAh + (size_t)rr * K + (k0) + c8);          \
            cp16(base + 16384 +  so, PAl + (size_t)rr * K + (k0) + c8);          \
            cp16(base + 32768 +  so, PBh + (size_t)rr * K + (k0) + c8);          \
            cp16(base + 49152 +  so, PBl + (size_t)rr * K + (k0) + c8);          \
        }                                                                        \
    }

    const int NC = K >> 6;
    LOAD_STAGE(0, 0);  cp_commit();
    LOAD_STAGE(1, 64); cp_commit();

    // ldmatrix lane offsets (within tile, before chunk/k16 offset)
    const uint32_t a_lrow = (lane & 15);
    const uint32_t a_lkb  = (lane >> 4) * 16;
    const uint32_t b_lrow = (lane & 7) + ((lane >> 3) & 1) * 8;

    for (int i = 0; i < NC; i++) {
        cp_wait1();
        __syncthreads();
        const uint32_t bA = sb + (i & 1) * STAGE_B;
        const uint32_t bB = bA + 32768;

#pragma unroll
        for (int ks = 0; ks < 4; ks++) {
            const uint32_t kb = ks * 32;
            uint32_t ah[2][4], al[2][4];
#pragma unroll
            for (int f = 0; f < 2; f++) {
                uint32_t off = (wm * 32 + f * 16 + a_lrow) * 128 + kb + a_lkb;
                ldsm4(ah[f][0], ah[f][1], ah[f][2], ah[f][3], bA + SWZ(off));
                ldsm4(al[f][0], al[f][1], al[f][2], al[f][3], bA + 16384 + SWZ(off));
            }
#pragma unroll
            for (int nf = 0; nf < 4; nf++) {
                uint32_t off = (wn * 64 + nf * 16 + b_lrow) * 128 + kb + a_lkb;
                uint32_t h0, h1, h2, h3, l0, l1, l2, l3;
                ldsm4(h0, h1, h2, h3, bB + SWZ(off));
                ldsm4(l0, l1, l2, l3, bB + 16384 + SWZ(off));
#pragma unroll
                for (int f = 0; f < 2; f++) {
                    mma16816(acc[f][nf * 2 + 0], ah[f], h0, h2);
                    mma16816(acc[f][nf * 2 + 0], ah[f], l0, l2);
                    mma16816(acc[f][nf * 2 + 0], al[f], h0, h2);
                    mma16816(acc[f][nf * 2 + 1], ah[f], h1, h3);
                    mma16816(acc[f][nf * 2 + 1], ah[f], l1, l3);
                    mma16816(acc[f][nf * 2 + 1], al[f], h1, h3);
                }
            }
        }
        __syncthreads();
        if (i + 2 < NC) LOAD_STAGE(i & 1, (i + 2) * 64);
        cp_commit();
    }
#undef LOAD_STAGE
}

// stage accumulators to SMEM as f32 [128][CSTRIDE]
__device__ __forceinline__ void store_acc(char* smem, float acc[2][8][4]) {
    float* Cs = (float*)smem;
    const int lane = threadIdx.x & 31, wid = threadIdx.x >> 5;
    const int wm = wid & 3, wn = wid >> 2;
#pragma unroll
    for (int f = 0; f < 2; f++)
#pragma unroll
        for (int nf2 = 0; nf2 < 8; nf2++) {
            int m = wm * 32 + f * 16 + (lane >> 2);
            int n = wn * 64 + nf2 * 8 + (lane & 3) * 2;
            Cs[m * CSTRIDE + n]           = acc[f][nf2][0];
            Cs[m * CSTRIDE + n + 1]       = acc[f][nf2][1];
            Cs[(m + 8) * CSTRIDE + n]     = acc[f][nf2][2];
            Cs[(m + 8) * CSTRIDE + n + 1] = acc[f][nf2][3];
        }
}

// ---- LSTM kernel: blob cols = [f(32) | i(32) | c(32) | o(32)] per CTA --------
__global__ void __launch_bounds__(256, 1)
lstm_gemm(const __nv_bfloat16* __restrict__ Ahi, const __nv_bfloat16* __restrict__ Alo,
          int K,
          const __nv_bfloat16* __restrict__ Whi, const __nv_bfloat16* __restrict__ Wlo,
          const float* __restrict__ bfp, const float* __restrict__ bip,
          const float* __restrict__ bcp, const float* __restrict__ bop,
          const float* __restrict__ c_old,
          float* __restrict__ h_out, float* __restrict__ c_out,
          __nv_bfloat16* __restrict__ nxh, __nv_bfloat16* __restrict__ nxl, int nxK)
{
    extern __shared__ __align__(1024) char smem[];
    float acc[2][8][4];
#pragma unroll
    for (int f = 0; f < 2; f++)
#pragma unroll
        for (int n = 0; n < 8; n++)
#pragma unroll
            for (int j = 0; j < 4; j++) acc[f][n][j] = 0.0f;

    const int m0 = blockIdx.y * 128;
    gemm_mainloop(Ahi, Alo, Whi, Wlo, K, m0, blockIdx.x * 128, smem, acc);
    __syncthreads();
    store_acc(smem, acc);
    __syncthreads();

    const float* Cs = (const float*)smem;
    const int tid = threadIdx.x;
    const int n0 = blockIdx.x * 32;
#pragma unroll
    for (int it = 0; it < 16; it++) {
        int e = tid + it * 256;
        int mr = e >> 5, nc = e & 31;
        int m = m0 + mr, n = n0 + nc;
        float fv = sigm(Cs[mr * CSTRIDE + nc]       + bfp[n]);
        float iv = sigm(Cs[mr * CSTRIDE + 32 + nc]  + bip[n]);
        float cd = tanhf(Cs[mr * CSTRIDE + 64 + nc] + bcp[n]);
        float ov = sigm(Cs[mr * CSTRIDE + 96 + nc]  + bop[n]);
        float hv = ov * tanhf(cd);                       // double tanh (reference)
        float cv = fv * c_old[(size_t)m * 1024 + n] + cd * iv;
        h_out[(size_t)m * 1024 + n] = hv;
        c_out[(size_t)m * 1024 + n] = cv;
        __nv_bfloat16 hh = __float2bfloat16(hv);
        nxh[(size_t)m * nxK + n] = hh;
        nxl[(size_t)m * nxK + n] = __float2bfloat16(hv - __bfloat162float(hh));
    }
}

// ---- MLP kernel: mode 1 = relu + bf16 split out; mode 0 = fp32 out -----------
__global__ void __launch_bounds__(256, 1)
mlp_gemm(const __nv_bfloat16* __restrict__ Ahi, const __nv_bfloat16* __restrict__ Alo,
         int K,
         const __nv_bfloat16* __restrict__ Whi, const __nv_bfloat16* __restrict__ Wlo,
         const float* __restrict__ bias, int mode,
         float* __restrict__ f32out,
         __nv_bfloat16* __restrict__ oh, __nv_bfloat16* __restrict__ ol, int ostride)
{
    extern __shared__ __align__(1024) char smem[];
    float acc[2][8][4];
#pragma unroll
    for (int f = 0; f < 2; f++)
#pragma unroll
        for (int n = 0; n < 8; n++)
#pragma unroll
            for (int j = 0; j < 4; j++) acc[f][n][j] = 0.0f;

    const int m0 = blockIdx.y * 128;
    const int n0 = blockIdx.x * 128;
    gemm_mainloop(Ahi, Alo, Whi, Wlo, K, m0, n0, smem, acc);
    __syncthreads();
    store_acc(smem, acc);
    __syncthreads();

    const float* Cs = (const float*)smem;
    const int tid = threadIdx.x;
#pragma unroll
    for (int it = 0; it < 64; it++) {
        int e = tid + it * 256;
        int mr = e >> 7, nc = e & 127;
        int m = m0 + mr, n = n0 + nc;
        float v = Cs[mr * CSTRIDE + nc] + bias[n];
        if (mode == 1) {
            v = fmaxf(v, 0.0f);
            __nv_bfloat16 hh = __float2bfloat16(v);
            oh[(size_t)m * ostride + n] = hh;
            ol[(size_t)m * ostride + n] = __float2bfloat16(v - __bfloat162float(hh));
        } else {
            f32out[(size_t)m * ostride + n] = v;
        }
    }
}

// ---- bf16 hi/lo split preprocessing ------------------------------------------
__global__ void split_act(const float* __restrict__ src,
                          __nv_bfloat16* __restrict__ dhi, __nv_bfloat16* __restrict__ dlo,
                          int rows, int cols, int dstK, int off)
{
    int idx = blockIdx.x * blockDim.x + threadIdx.x;
    int tot = rows * (cols >> 2);
    if (idx >= tot) return;
    int r = idx / (cols >> 2);
    int c = (idx % (cols >> 2)) << 2;
    float4 v = *(const float4*)(src + (size_t)r * cols + c);
    size_t d = (size_t)r * dstK + off + c;
    float a[4] = {v.x, v.y, v.z, v.w};
#pragma unroll
    for (int k = 0; k < 4; k++) {
        __nv_bfloat16 h = __float2bfloat16(a[k]);
        dhi[d + k] = h;
        dlo[d + k] = __float2bfloat16(a[k] - __bfloat162float(h));
    }
}

// weight split with gate interleave (granularity 32):
// blob row = (n/32)*(gates*32) + g*32 + n%32   (gates=1 -> identity)
__global__ void split_wgt(const float* __restrict__ src,
                          __nv_bfloat16* __restrict__ dhi, __nv_bfloat16* __restrict__ dlo,
                          int N, int K, int g, int gates)
{
    int idx = blockIdx.x * blockDim.x + threadIdx.x;
    int tot = N * (K >> 2);
    if (idx >= tot) return;
    int n = idx / (K >> 2);
    int c = (idx % (K >> 2)) << 2;
    int outr = (n >> 5) * (gates << 5) + (g << 5) + (n & 31);
    float4 v = *(const float4*)(src + (size_t)n * K + c);
    size_t d = (size_t)outr * K + c;
    float a[4] = {v.x, v.y, v.z, v.w};
#pragma unroll
    for (int k = 0; k < 4; k++) {
        __nv_bfloat16 h = __float2bfloat16(a[k]);
        dhi[d + k] = h;
        dlo[d + k] = __float2bfloat16(a[k] - __bfloat162float(h));
    }
}

// ---- launch --------------------------------------------------------------------
extern "C" void kernel_launch(void* const* d_in, const int* in_sizes, int n_in,
                              void* d_out, int out_size) {
    (void)in_sizes; (void)n_in; (void)out_size;
    const float* X    = (const float*)d_in[0];
    const float* h1in = (const float*)d_in[1];
    const float* h2in = (const float*)d_in[2];
    const float* c1in = (const float*)d_in[3];
    const float* c2in = (const float*)d_in[4];
    const float* Wf1 = (const float*)d_in[5];  const float* bf1 = (const float*)d_in[6];
    const float* Wi1 = (const float*)d_in[7];  const float* bi1 = (const float*)d_in[8];
    const float* Wc1 = (const float*)d_in[9];  const float* bc1 = (const float*)d_in[10];
    const float* Wo1 = (const float*)d_in[11]; const float* bo1 = (const float*)d_in[12];
    const float* Wf2 = (const float*)d_in[13]; const float* bf2 = (const float*)d_in[14];
    const float* Wi2 = (const float*)d_in[15]; const float* bi2 = (const float*)d_in[16];
    const float* Wc2 = (const float*)d_in[17]; const float* bc2 = (const float*)d_in[18];
    const float* Wo2 = (const float*)d_in[19]; const float* bo2 = (const float*)d_in[20];
    const float* W3  = (const float*)d_in[21]; const float* b3  = (const float*)d_in[22];
    const float* W4  = (const float*)d_in[23]; const float* b4  = (const float*)d_in[24];

    float* out  = (float*)d_out;
    float* o_h1 = out  + (size_t)4096 * 1024;
    float* o_h2 = o_h1 + (size_t)4096 * 1024;
    float* o_c1 = o_h2 + (size_t)4096 * 1024;
    float* o_c2 = o_c1 + (size_t)4096 * 1024;

    void *pw, *pa1, *pa2, *ph2, *po3;
    cudaGetSymbolAddress(&pw,  g_w);
    cudaGetSymbolAddress(&pa1, g_A1s);
    cudaGetSymbolAddress(&pa2, g_A2s);
    cudaGetSymbolAddress(&ph2, g_h2s);
    cudaGetSymbolAddress(&po3, g_o3s);
    __nv_bfloat16* W   = (__nv_bfloat16*)pw;
    __nv_bfloat16* A1h = (__nv_bfloat16*)pa1;  __nv_bfloat16* A1l = A1h + 8388608;
    __nv_bfloat16* A2h = (__nv_bfloat16*)pa2;  __nv_bfloat16* A2l = A2h + 8388608;
    __nv_bfloat16* H2h = (__nv_bfloat16*)ph2;  __nv_bfloat16* H2l = H2h + 4194304;
    __nv_bfloat16* O3h = (__nv_bfloat16*)po3;  __nv_bfloat16* O3l = O3h + 8388608;
    __nv_bfloat16 *W1h = W,            *W1l = W + 8388608;
    __nv_bfloat16 *W2h = W + 16777216, *W2l = W + 25165824;
    __nv_bfloat16 *W3h = W + 33554432, *W3l = W + 35651584;
    __nv_bfloat16 *W4h = W + 37748736, *W4l = W + 39845888;

    cudaFuncSetAttribute(lstm_gemm, cudaFuncAttributeMaxDynamicSharedMemorySize, SMEM_BYTES);
    cudaFuncSetAttribute(mlp_gemm,  cudaFuncAttributeMaxDynamicSharedMemorySize, SMEM_BYTES);

    // weight splits (gate-interleaved blobs)
    split_wgt<<<2048, 256>>>(Wf1, W1h, W1l, 1024, 2048, 0, 4);
    split_wgt<<<2048, 256>>>(Wi1, W1h, W1l, 1024, 2048, 1, 4);
    split_wgt<<<2048, 256>>>(Wc1, W1h, W1l, 1024, 2048, 2, 4);
    split_wgt<<<2048, 256>>>(Wo1, W1h, W1l, 1024, 2048, 3, 4);
    split_wgt<<<2048, 256>>>(Wf2, W2h, W2l, 1024, 2048, 0, 4);
    split_wgt<<<2048, 256>>>(Wi2, W2h, W2l, 1024, 2048, 1, 4);
    split_wgt<<<2048, 256>>>(Wc2, W2h, W2l, 1024, 2048, 2, 4);
    split_wgt<<<2048, 256>>>(Wo2, W2h, W2l, 1024, 2048, 3, 4);
    split_wgt<<<2048, 256>>>(W3,  W3h, W3l, 2048, 1024, 0, 1);
    split_wgt<<<2048, 256>>>(W4,  W4h, W4l, 1024, 2048, 0, 1);
    // activation splits
    split_act<<<4096, 256>>>(X,    A1h, A1l, 4096, 1024, 2048, 0);
    split_act<<<4096, 256>>>(h1in, A1h, A1l, 4096, 1024, 2048, 1024);
    split_act<<<4096, 256>>>(h2in, A2h, A2l, 4096, 1024, 2048, 1024);

    // LSTM1: z=[X|h1_in], K=2048; writes h1 splits into A2 cols 0..1023
    lstm_gemm<<<dim3(32, 32), 256, SMEM_BYTES>>>(
        A1h, A1l, 2048, W1h, W1l, bf1, bi1, bc1, bo1,
        c1in, o_h1, o_c1, A2h, A2l, 2048);
    // LSTM2: z=[h1|h2_in], K=2048; writes h2 splits
    lstm_gemm<<<dim3(32, 32), 256, SMEM_BYTES>>>(
        A2h, A2l, 2048, W2h, W2l, bf2, bi2, bc2, bo2,
        c2in, o_h2, o_c2, H2h, H2l, 1024);
    // MLP1: out3 = relu(h2 @ W3^T + b3) -> bf16 splits
    mlp_gemm<<<dim3(16, 32), 256, SMEM_BYTES>>>(
        H2h, H2l, 1024, W3h, W3l, b3, 1, nullptr, O3h, O3l, 2048);
    // MLP2: out = out3 @ W4^T + b4 -> fp32
    mlp_gemm<<<dim3(8, 32), 256, SMEM_BYTES>>>(
        O3h, O3l, 2048, W4h, W4l, b4, 0, out, nullptr, nullptr, 1024);
}

// round 5
// speedup vs baseline: 5.0962x; 1.0048x over previous
#include <cuda_runtime.h>
#include <cuda_bf16.h>
#include <math.h>
#include <stdint.h>

// ============================================================================
// QueST: 2-layer LSTM cell + 2-layer MLP head, fp32 semantics.
// Engine: mma.sync.m16n8k16 bf16 (tcgen05 rejected by harness's compute_103
// PTX pass), bf16x3 split for fp32-class accuracy.
// CTA tile 128x128, warp tile 32x64, cp.async 3-stage pipeline, K=64 chunks.
// ============================================================================

#define SWZ(o)     ((o) ^ (((o) >> 3) & 0x70))
#define STAGE_B    65536                 // Ahi 16K | Alo 16K | Bhi 16K | Blo 16K
#define NSTAGE     3
#define SMEM_BYTES (NSTAGE * STAGE_B)    // 196608
#define CSTRIDE    132                   // epilogue f32 stage stride (pad 4)

// ---- scratch (no cudaMalloc allowed) ---------------------------------------
__device__ __nv_bfloat16 g_w[41943040];    // weight splits: W1(hi,lo) W2 W3 W4
__device__ __nv_bfloat16 g_A1s[16777216];  // [4096,2048] hi + lo   (X | h1_in)
__device__ __nv_bfloat16 g_A2s[16777216];  // [4096,2048] hi + lo   (h1 | h2_in)
__device__ __nv_bfloat16 g_h2s[8388608];   // [4096,1024] hi + lo
__device__ __nv_bfloat16 g_o3s[16777216];  // [4096,2048] hi + lo

// ---- helpers -----------------------------------------------------------------
__device__ __forceinline__ uint32_t smem_u32(const void* p) {
    uint32_t a;
    asm("{ .reg .u64 t; cvta.to.shared.u64 t, %1; cvt.u32.u64 %0, t; }"
        : "=r"(a) : "l"(p));
    return a;
}
__device__ __forceinline__ void cp16(uint32_t dst, const void* src) {
    asm volatile("cp.async.cg.shared.global [%0], [%1], 16;" :: "r"(dst), "l"(src));
}
__device__ __forceinline__ void cp_commit() {
    asm volatile("cp.async.commit_group;" ::: "memory");
}
__device__ __forceinline__ void cp_waitN() {
    asm volatile("cp.async.wait_group %0;" :: "n"(NSTAGE - 1) : "memory");
}
__device__ __forceinline__ void ldsm4(uint32_t& r0, uint32_t& r1, uint32_t& r2,
                                      uint32_t& r3, uint32_t a) {
    asm volatile("ldmatrix.sync.aligned.m8n8.x4.shared.b16 {%0,%1,%2,%3}, [%4];"
                 : "=r"(r0), "=r"(r1), "=r"(r2), "=r"(r3) : "r"(a));
}
__device__ __forceinline__ void mma16816(float* d, const uint32_t* a,
                                         uint32_t b0, uint32_t b1) {
    asm volatile(
        "mma.sync.aligned.m16n8k16.row.col.f32.bf16.bf16.f32 "
        "{%0,%1,%2,%3}, {%4,%5,%6,%7}, {%8,%9}, {%0,%1,%2,%3};"
        : "+f"(d[0]), "+f"(d[1]), "+f"(d[2]), "+f"(d[3])
        : "r"(a[0]), "r"(a[1]), "r"(a[2]), "r"(a[3]), "r"(b0), "r"(b1));
}
__device__ __forceinline__ float sigm(float x) { return 1.0f / (1.0f + expf(-x)); }

// ---- GEMM mainloop: acc[128,128] += A[128,K] * Wblob[128,K]^T (bf16x3) -------
__device__ __forceinline__ void gemm_mainloop(
    const __nv_bfloat16* __restrict__ Ahi, const __nv_bfloat16* __restrict__ Alo,
    const __nv_bfloat16* __restrict__ Bhi, const __nv_bfloat16* __restrict__ Blo,
    int K, int m0, int n0b, char* smem, float acc[2][8][4])
{
    const uint32_t sb = smem_u32(smem);
    const int tid  = threadIdx.x;
    const int lane = tid & 31;
    const int wid  = tid >> 5;
    const int wm   = wid & 3;    // m-warp 0..3 -> 32 rows each
    const int wn   = wid >> 2;   // n-warp 0..1 -> 64 cols each

    const __nv_bfloat16* PAh = Ahi + (size_t)m0 * K;
    const __nv_bfloat16* PAl = Alo + (size_t)m0 * K;
    const __nv_bfloat16* PBh = Bhi + (size_t)n0b * K;
    const __nv_bfloat16* PBl = Blo + (size_t)n0b * K;

    const int r  = tid >> 3;          // 0..31
    const int c8 = (tid & 7) * 8;     // k element offset (16B chunks)

#define LOAD_STAGE(buf, k0)                                                      \
    {                                                                            \
        uint32_t base = sb + (buf) * STAGE_B;                                    \
        _Pragma("unroll")                                                        \
        for (int it = 0; it < 4; it++) {                                         \
            int rr = r + it * 32;                                                \
            uint32_t so = SWZ(rr * 128 + c8 * 2);                                \
            cp16(base +          so, PAh + (size_t)rr * K + (k0) + c8);          \
            cp16(base + 16384 +  so, PAl + (size_t)rr * K + (k0) + c8);          \
            cp16(base + 32768 +  so, PBh + (size_t)rr * K + (k0) + c8);          \
            cp16(base + 49152 +  so, PBl + (size_t)rr * K + (k0) + c8);          \
        }                                                                        \
    }

    const int NC = K >> 6;            // 16 or 32 -> always >= NSTAGE
#pragma unroll
    for (int s = 0; s < NSTAGE; s++) { LOAD_STAGE(s, s * 64); cp_commit(); }

    const uint32_t a_lrow = (lane & 15);
    const uint32_t a_lkb  = (lane >> 4) * 16;
    const uint32_t b_lrow = (lane & 7) + ((lane >> 3) & 1) * 8;

    int buf = 0;
    for (int i = 0; i < NC; i++) {
        cp_waitN();
        __syncthreads();
        const uint32_t bA = sb + buf * STAGE_B;
        const uint32_t bB = bA + 32768;

#pragma unroll
        for (int ks = 0; ks < 4; ks++) {
            const uint32_t kb = ks * 32;
            uint32_t ah[2][4], al[2][4];
#pragma unroll
            for (int f = 0; f < 2; f++) {
                uint32_t off = (wm * 32 + f * 16 + a_lrow) * 128 + kb + a_lkb;
                ldsm4(ah[f][0], ah[f][1], ah[f][2], ah[f][3], bA + SWZ(off));
                ldsm4(al[f][0], al[f][1], al[f][2], al[f][3], bA + 16384 + SWZ(off));
            }
#pragma unroll
            for (int nf = 0; nf < 4; nf++) {
                uint32_t off = (wn * 64 + nf * 16 + b_lrow) * 128 + kb + a_lkb;
                uint32_t h0, h1, h2, h3, l0, l1, l2, l3;
                ldsm4(h0, h1, h2, h3, bB + SWZ(off));
                ldsm4(l0, l1, l2, l3, bB + 16384 + SWZ(off));
#pragma unroll
                for (int f = 0; f < 2; f++) {
                    mma16816(acc[f][nf * 2 + 0], ah[f], h0, h2);
                    mma16816(acc[f][nf * 2 + 0], ah[f], l0, l2);
                    mma16816(acc[f][nf * 2 + 0], al[f], h0, h2);
                    mma16816(acc[f][nf * 2 + 1], ah[f], h1, h3);
                    mma16816(acc[f][nf * 2 + 1], ah[f], l1, l3);
                    mma16816(acc[f][nf * 2 + 1], al[f], h1, h3);
                }
            }
        }
        __syncthreads();
        if (i + NSTAGE < NC) LOAD_STAGE(buf, (i + NSTAGE) * 64);
        cp_commit();
        buf = (buf == NSTAGE - 1) ? 0 : buf + 1;
    }
#undef LOAD_STAGE
}

// stage accumulators to SMEM as f32 [128][CSTRIDE]
__device__ __forceinline__ void store_acc(char* smem, float acc[2][8][4]) {
    float* Cs = (float*)smem;
    const int lane = threadIdx.x & 31, wid = threadIdx.x >> 5;
    const int wm = wid & 3, wn = wid >> 2;
#pragma unroll
    for (int f = 0; f < 2; f++)
#pragma unroll
        for (int nf2 = 0; nf2 < 8; nf2++) {
            int m = wm * 32 + f * 16 + (lane >> 2);
            int n = wn * 64 + nf2 * 8 + (lane & 3) * 2;
            Cs[m * CSTRIDE + n]           = acc[f][nf2][0];
            Cs[m * CSTRIDE + n + 1]       = acc[f][nf2][1];
            Cs[(m + 8) * CSTRIDE + n]     = acc[f][nf2][2];
            Cs[(m + 8) * CSTRIDE + n + 1] = acc[f][nf2][3];
        }
}

// ---- LSTM kernel: blob cols = [f(32) | i(32) | c(32) | o(32)] per CTA --------
__global__ void __launch_bounds__(256, 1)
lstm_gemm(const __nv_bfloat16* __restrict__ Ahi, const __nv_bfloat16* __restrict__ Alo,
          int K,
          const __nv_bfloat16* __restrict__ Whi, const __nv_bfloat16* __restrict__ Wlo,
          const float* __restrict__ bfp, const float* __restrict__ bip,
          const float* __restrict__ bcp, const float* __restrict__ bop,
          const float* __restrict__ c_old,
          float* __restrict__ h_out, float* __restrict__ c_out,
          __nv_bfloat16* __restrict__ nxh, __nv_bfloat16* __restrict__ nxl, int nxK)
{
    extern __shared__ __align__(1024) char smem[];
    float acc[2][8][4];
#pragma unroll
    for (int f = 0; f < 2; f++)
#pragma unroll
        for (int n = 0; n < 8; n++)
#pragma unroll
            for (int j = 0; j < 4; j++) acc[f][n][j] = 0.0f;

    const int m0 = blockIdx.y * 128;
    gemm_mainloop(Ahi, Alo, Whi, Wlo, K, m0, blockIdx.x * 128, smem, acc);
    __syncthreads();
    store_acc(smem, acc);
    __syncthreads();

    const float* Cs = (const float*)smem;
    const int tid = threadIdx.x;
    const int n0 = blockIdx.x * 32;
#pragma unroll
    for (int it = 0; it < 16; it++) {
        int e = tid + it * 256;
        int mr = e >> 5, nc = e & 31;
        int m = m0 + mr, n = n0 + nc;
        float fv = sigm(Cs[mr * CSTRIDE + nc]       + bfp[n]);
        float iv = sigm(Cs[mr * CSTRIDE + 32 + nc]  + bip[n]);
        float cd = tanhf(Cs[mr * CSTRIDE + 64 + nc] + bcp[n]);
        float ov = sigm(Cs[mr * CSTRIDE + 96 + nc]  + bop[n]);
        float hv = ov * tanhf(cd);                       // double tanh (reference)
        float cv = fv * c_old[(size_t)m * 1024 + n] + cd * iv;
        h_out[(size_t)m * 1024 + n] = hv;
        c_out[(size_t)m * 1024 + n] = cv;
        __nv_bfloat16 hh = __float2bfloat16(hv);
        nxh[(size_t)m * nxK + n] = hh;
        nxl[(size_t)m * nxK + n] = __float2bfloat16(hv - __bfloat162float(hh));
    }
}

// ---- MLP kernel: mode 1 = relu + bf16 split out; mode 0 = fp32 out -----------
__global__ void __launch_bounds__(256, 1)
mlp_gemm(const __nv_bfloat16* __restrict__ Ahi, const __nv_bfloat16* __restrict__ Alo,
         int K,
         const __nv_bfloat16* __restrict__ Whi, const __nv_bfloat16* __restrict__ Wlo,
         const float* __restrict__ bias, int mode,
         float* __restrict__ f32out,
         __nv_bfloat16* __restrict__ oh, __nv_bfloat16* __restrict__ ol, int ostride)
{
    extern __shared__ __align__(1024) char smem[];
    float acc[2][8][4];
#pragma unroll
    for (int f = 0; f < 2; f++)
#pragma unroll
        for (int n = 0; n < 8; n++)
#pragma unroll
            for (int j = 0; j < 4; j++) acc[f][n][j] = 0.0f;

    const int m0 = blockIdx.y * 128;
    const int n0 = blockIdx.x * 128;
    gemm_mainloop(Ahi, Alo, Whi, Wlo, K, m0, n0, smem, acc);
    __syncthreads();
    store_acc(smem, acc);
    __syncthreads();

    const float* Cs = (const float*)smem;
    const int tid = threadIdx.x;
#pragma unroll
    for (int it = 0; it < 64; it++) {
        int e = tid + it * 256;
        int mr = e >> 7, nc = e & 127;
        int m = m0 + mr, n = n0 + nc;
        float v = Cs[mr * CSTRIDE + nc] + bias[n];
        if (mode == 1) {
            v = fmaxf(v, 0.0f);
            __nv_bfloat16 hh = __float2bfloat16(v);
            oh[(size_t)m * ostride + n] = hh;
            ol[(size_t)m * ostride + n] = __float2bfloat16(v - __bfloat162float(hh));
        } else {
            f32out[(size_t)m * ostride + n] = v;
        }
    }
}

// ---- merged bf16 hi/lo split pre-passes (2 launches total) --------------------
struct WEnt { const float* src; __nv_bfloat16* dhi; __nv_bfloat16* dlo;
              int K, g, gates; };
struct WPack { WEnt m[10]; };

// all 10 weight matrices are exactly 2M elements -> grid (2048, 10) x 256 thr
__global__ void __launch_bounds__(256)
split_wgt_all(WPack P)
{
    const WEnt w = P.m[blockIdx.y];
    int idx = blockIdx.x * 256 + threadIdx.x;        // 0..524287 (x4 elems)
    const int kq = w.K >> 2;
    const int ksh = (w.K == 2048) ? 9 : 8;
    int n = idx >> ksh;
    int c = (idx & (kq - 1)) << 2;
    int outr = (n >> 5) * (w.gates << 5) + (w.g << 5) + (n & 31);
    float4 v = *(const float4*)(w.src + (size_t)n * w.K + c);
    size_t d = (size_t)outr * w.K + c;
    float a[4] = {v.x, v.y, v.z, v.w};
#pragma unroll
    for (int k = 0; k < 4; k++) {
        __nv_bfloat16 h = __float2bfloat16(a[k]);
        w.dhi[d + k] = h;
        w.dlo[d + k] = __float2bfloat16(a[k] - __bfloat162float(h));
    }
}

struct AEnt { const float* src; __nv_bfloat16* dhi; __nv_bfloat16* dlo; int off; };
struct APack { AEnt m[3]; };

// 3 activation matrices, each [4096,1024], dstK = 2048 -> grid (4096, 3)
__global__ void __launch_bounds__(256)
split_act_all(APack P)
{
    const AEnt a = P.m[blockIdx.y];
    int idx = blockIdx.x * 256 + threadIdx.x;        // 0..1048575 (x4 elems)
    int r = idx >> 8;
    int c = (idx & 255) << 2;
    float4 v = *(const float4*)(a.src + (size_t)r * 1024 + c);
    size_t d = (size_t)r * 2048 + a.off + c;
    float x[4] = {v.x, v.y, v.z, v.w};
#pragma unroll
    for (int k = 0; k < 4; k++) {
        __nv_bfloat16 h = __float2bfloat16(x[k]);
        a.dhi[d + k] = h;
        a.dlo[d + k] = __float2bfloat16(x[k] - __bfloat162float(h));
    }
}

// ---- launch --------------------------------------------------------------------
extern "C" void kernel_launch(void* const* d_in, const int* in_sizes, int n_in,
                              void* d_out, int out_size) {
    (void)in_sizes; (void)n_in; (void)out_size;
    const float* X    = (const float*)d_in[0];
    const float* h1in = (const float*)d_in[1];
    const float* h2in = (const float*)d_in[2];
    const float* c1in = (const float*)d_in[3];
    const float* c2in = (const float*)d_in[4];
    const float* Wf1 = (const float*)d_in[5];  const float* bf1 = (const float*)d_in[6];
    const float* Wi1 = (const float*)d_in[7];  const float* bi1 = (const float*)d_in[8];
    const float* Wc1 = (const float*)d_in[9];  const float* bc1 = (const float*)d_in[10];
    const float* Wo1 = (const float*)d_in[11]; const float* bo1 = (const float*)d_in[12];
    const float* Wf2 = (const float*)d_in[13]; const float* bf2 = (const float*)d_in[14];
    const float* Wi2 = (const float*)d_in[15]; const float* bi2 = (const float*)d_in[16];
    const float* Wc2 = (const float*)d_in[17]; const float* bc2 = (const float*)d_in[18];
    const float* Wo2 = (const float*)d_in[19]; const float* bo2 = (const float*)d_in[20];
    const float* W3  = (const float*)d_in[21]; const float* b3  = (const float*)d_in[22];
    const float* W4  = (const float*)d_in[23]; const float* b4  = (const float*)d_in[24];

    float* out  = (float*)d_out;
    float* o_h1 = out  + (size_t)4096 * 1024;
    float* o_h2 = o_h1 + (size_t)4096 * 1024;
    float* o_c1 = o_h2 + (size_t)4096 * 1024;
    float* o_c2 = o_c1 + (size_t)4096 * 1024;

    void *pw, *pa1, *pa2, *ph2, *po3;
    cudaGetSymbolAddress(&pw,  g_w);
    cudaGetSymbolAddress(&pa1, g_A1s);
    cudaGetSymbolAddress(&pa2, g_A2s);
    cudaGetSymbolAddress(&ph2, g_h2s);
    cudaGetSymbolAddress(&po3, g_o3s);
    __nv_bfloat16* W   = (__nv_bfloat16*)pw;
    __nv_bfloat16* A1h = (__nv_bfloat16*)pa1;  __nv_bfloat16* A1l = A1h + 8388608;
    __nv_bfloat16* A2h = (__nv_bfloat16*)pa2;  __nv_bfloat16* A2l = A2h + 8388608;
    __nv_bfloat16* H2h = (__nv_bfloat16*)ph2;  __nv_bfloat16* H2l = H2h + 4194304;
    __nv_bfloat16* O3h = (__nv_bfloat16*)po3;  __nv_bfloat16* O3l = O3h + 8388608;
    __nv_bfloat16 *W1h = W,            *W1l = W + 8388608;
    __nv_bfloat16 *W2h = W + 16777216, *W2l = W + 25165824;
    __nv_bfloat16 *W3h = W + 33554432, *W3l = W + 35651584;
    __nv_bfloat16 *W4h = W + 37748736, *W4l = W + 39845888;

    cudaFuncSetAttribute(lstm_gemm, cudaFuncAttributeMaxDynamicSharedMemorySize, SMEM_BYTES);
    cudaFuncSetAttribute(mlp_gemm,  cudaFuncAttributeMaxDynamicSharedMemorySize, SMEM_BYTES);

    // launch 0: all weight splits (gate-interleaved blobs)
    WPack wp = {{
        {Wf1, W1h, W1l, 2048, 0, 4}, {Wi1, W1h, W1l, 2048, 1, 4},
        {Wc1, W1h, W1l, 2048, 2, 4}, {Wo1, W1h, W1l, 2048, 3, 4},
        {Wf2, W2h, W2l, 2048, 0, 4}, {Wi2, W2h, W2l, 2048, 1, 4},
        {Wc2, W2h, W2l, 2048, 2, 4}, {Wo2, W2h, W2l, 2048, 3, 4},
        {W3,  W3h, W3l, 1024, 0, 1}, {W4,  W4h, W4l, 2048, 0, 1},
    }};
    split_wgt_all<<<dim3(2048, 10), 256>>>(wp);

    // launch 1: all activation splits
    APack ap = {{
        {X,    A1h, A1l, 0},
        {h1in, A1h, A1l, 1024},
        {h2in, A2h, A2l, 1024},
    }};
    split_act_all<<<dim3(4096, 3), 256>>>(ap);

    // launch 2: LSTM1: z=[X|h1_in], K=2048; writes h1 splits into A2 cols 0..1023
    lstm_gemm<<<dim3(32, 32), 256, SMEM_BYTES>>>(
        A1h, A1l, 2048, W1h, W1l, bf1, bi1, bc1, bo1,
        c1in, o_h1, o_c1, A2h, A2l, 2048);
    // launch 3: LSTM2: z=[h1|h2_in], K=2048; writes h2 splits
    lstm_gemm<<<dim3(32, 32), 256, SMEM_BYTES>>>(
        A2h, A2l, 2048, W2h, W2l, bf2, bi2, bc2, bo2,
        c2in, o_h2, o_c2, H2h, H2l, 1024);
    // launch 4: MLP1: out3 = relu(h2 @ W3^T + b3) -> bf16 splits
    mlp_gemm<<<dim3(16, 32), 256, SMEM_BYTES>>>(
        H2h, H2l, 1024, W3h, W3l, b3, 1, nullptr, O3h, O3l, 2048);
    // launch 5: MLP2: out = out3 @ W4^T + b4 -> fp32   (profiled by -s 5)
    mlp_gemm<<<dim3(8, 32), 256, SMEM_BYTES>>>(
        O3h, O3l, 2048, W4h, W4l, b4, 0, out, nullptr, nullptr, 1024);
}